// round 3
// baseline (speedup 1.0000x reference)
#include <cuda_runtime.h>
#include <cuda_bf16.h>
#include <cstdint>

// 3D Haar DWT, x: (B=2, C=32, D=64, H=128, W=128) fp32
// out: low (2,32,32,64,64) then highs (2,32,7,32,64,64), packed.
//
// R3: 256-bit loads/stores (sm_100+ v8.f32). Each thread: 8 output-w sites
// for one (bc,d,h) -> loads 4 rows x 16 floats (2x LDG.256 each), writes
// 8 subbands x 1x STG.256. Warp store = 1KB contiguous.

#define C_HAAR 0.35355339059327373f  // 1/(2*sqrt(2))

__device__ __forceinline__ void ldg256(const float* p, float* v)
{
    asm volatile(
        "ld.global.v8.f32 {%0,%1,%2,%3,%4,%5,%6,%7}, [%8];"
        : "=f"(v[0]), "=f"(v[1]), "=f"(v[2]), "=f"(v[3]),
          "=f"(v[4]), "=f"(v[5]), "=f"(v[6]), "=f"(v[7])
        : "l"(p));
}

__device__ __forceinline__ void stg256(float* p, const float* v)
{
    asm volatile(
        "st.global.v8.f32 [%0], {%1,%2,%3,%4,%5,%6,%7,%8};"
        :: "l"(p),
           "f"(v[0]), "f"(v[1]), "f"(v[2]), "f"(v[3]),
           "f"(v[4]), "f"(v[5]), "f"(v[6]), "f"(v[7])
        : "memory");
}

__global__ __launch_bounds__(256) void dwt3d_haar_kernel(
    const float* __restrict__ x, float* __restrict__ out)
{
    // total threads = 1,048,576 = 64(bc) * 32(d) * 64(h) * 8(wg)
    unsigned tid = blockIdx.x * 256u + threadIdx.x;
    unsigned wg = tid & 7u;           // w-group: 8 output w per group
    unsigned h  = (tid >> 3) & 63u;   // output h (0..63)
    unsigned d  = (tid >> 9) & 31u;   // output d (0..31)
    unsigned bc = tid >> 14;          // b*C + c (0..63)

    // input: ((bc)*64 + 2d+i)*16384 + (2h+j)*128 + 16*wg
    size_t in_base = ((size_t)bc << 20)
                   + ((size_t)d << 15)    // 2d * 16384
                   + ((size_t)h << 8)     // 2h * 128
                   + (wg << 4);           // 16*wg

    // Load 4 rows (i,j in {0,1}^2), 16 contiguous floats each (2x LDG.256)
    float r[4][16];
#pragma unroll
    for (int i = 0; i < 2; i++) {
#pragma unroll
        for (int j = 0; j < 2; j++) {
            const float* p = x + in_base + (size_t)i * 16384 + (size_t)j * 128;
            ldg256(p,     &r[i * 2 + j][0]);
            ldg256(p + 8, &r[i * 2 + j][8]);
        }
    }

    // o[s][m]: subband s (i*4 + j*2 + k bits), output site m (0..7)
    float o[8][8];

#pragma unroll
    for (int m = 0; m < 8; m++) {
        float ka[2][2], kb[2][2];  // k-stage sum/diff per (i,j) row
#pragma unroll
        for (int i = 0; i < 2; i++) {
#pragma unroll
            for (int j = 0; j < 2; j++) {
                float v0 = r[i * 2 + j][2 * m];
                float v1 = r[i * 2 + j][2 * m + 1];
                ka[i][j] = v0 + v1;
                kb[i][j] = v0 - v1;
            }
        }
        float t[2][2][2];  // t[x][y][i]: after j-stage
#pragma unroll
        for (int i = 0; i < 2; i++) {
            t[0][0][i] = ka[i][0] + ka[i][1];
            t[0][1][i] = ka[i][0] - ka[i][1];
            t[1][0][i] = kb[i][0] + kb[i][1];
            t[1][1][i] = kb[i][0] - kb[i][1];
        }
#pragma unroll
        for (int y = 0; y < 2; y++) {
#pragma unroll
            for (int xk = 0; xk < 2; xk++) {
                o[0 * 4 + y * 2 + xk][m] = C_HAAR * (t[xk][y][0] + t[xk][y][1]);
                o[1 * 4 + y * 2 + xk][m] = C_HAAR * (t[xk][y][0] - t[xk][y][1]);
            }
        }
    }

    // Output: spatial = d*4096 + h*64 + 8*wg
    unsigned spatial = (d << 12) + (h << 6) + (wg << 3);

    // low: out[bc*131072 + spatial]
    stg256(out + ((size_t)bc << 17) + spatial, o[0]);

    // highs: out[8388608 + (bc*7 + (s-1))*131072 + spatial]
#pragma unroll
    for (int s = 1; s < 8; s++) {
        size_t off = 8388608u + ((size_t)(bc * 7u + (unsigned)(s - 1)) << 17) + spatial;
        stg256(out + off, o[s]);
    }
}

extern "C" void kernel_launch(void* const* d_in, const int* in_sizes, int n_in,
                              void* d_out, int out_size)
{
    const float* x = (const float*)d_in[0];
    float* out = (float*)d_out;
    // 1,048,576 threads / 256 = 4096 blocks
    dwt3d_haar_kernel<<<4096, 256>>>(x, out);
}